// round 4
// baseline (speedup 1.0000x reference)
#include <cuda_runtime.h>
#include <cstdint>

// ---------------- problem constants ----------------
#define DI     2048            // d_inner
#define DM     1024            // d_model
#define LSEQ   4096            // L
#define BQ     4               // batch
#define MTOT   (BQ*LSEQ)       // 16384 rows
#define DSTATE 16
#define DTR    65              // dt_rank
#define NPAR   97              // dt_rank + 2*d_state

// ---------------- scratch (device globals; allocation-free) ----------------
__device__ float g_xz[(size_t)MTOT * 4096];   // 256 MiB: [x_in | z]
__device__ float g_u[(size_t)MTOT * DI];      // 128 MiB: silu(conv(x_in))
__device__ float g_delta[(size_t)MTOT * DI];  // 128 MiB: dt proj -> softplus (in place)
__device__ float g_params[(size_t)MTOT * NPAR];
__device__ float g_ya[(size_t)MTOT * 4096];   // 256 MiB: [y_ssm | silu(z)]

// ---------------- tiny PTX helpers ----------------
__device__ __forceinline__ void cp16(void* sm, const void* gm, bool p) {
    unsigned s = (unsigned)__cvta_generic_to_shared(sm);
    int n = p ? 16 : 0;
    asm volatile("cp.async.ca.shared.global [%0], [%1], 16, %2;\n" ::"r"(s), "l"(gm), "r"(n));
}
__device__ __forceinline__ void cp4(void* sm, const void* gm, bool p) {
    unsigned s = (unsigned)__cvta_generic_to_shared(sm);
    int n = p ? 4 : 0;
    asm volatile("cp.async.ca.shared.global [%0], [%1], 4, %2;\n" ::"r"(s), "l"(gm), "r"(n));
}
#define CP_COMMIT asm volatile("cp.async.commit_group;\n" ::: "memory")
#define CP_WAIT1  asm volatile("cp.async.wait_group 1;\n" ::: "memory")
#define CP_WAIT0  asm volatile("cp.async.wait_group 0;\n" ::: "memory")

__device__ __forceinline__ unsigned f2tf(float x) {
    unsigned r;
    asm("cvt.rna.tf32.f32 %0, %1;" : "=r"(r) : "f"(x));
    return r;
}
__device__ __forceinline__ void mma8(float c[4], const unsigned a[4], const unsigned b[2]) {
    asm volatile(
        "mma.sync.aligned.m16n8k8.row.col.f32.tf32.tf32.f32 "
        "{%0,%1,%2,%3}, {%4,%5,%6,%7}, {%8,%9}, {%0,%1,%2,%3};\n"
        : "+f"(c[0]), "+f"(c[1]), "+f"(c[2]), "+f"(c[3])
        : "r"(a[0]), "r"(a[1]), "r"(a[2]), "r"(a[3]), "r"(b[0]), "r"(b[1]));
}

// ---------------- generic TN GEMM: C[m,n] = sum_k A[m,k]*B[n,k]  (tf32 mma) ----------
// VEC=true : lda/ldb 16B-aligned rows, K % 16 == 0 (float4 cp.async)
// VEC=false: scalar cp.async, ragged K supported
template <bool VEC>
__global__ __launch_bounds__(256) void gemm_tn(
    const float* __restrict__ A, const float* __restrict__ B, float* __restrict__ C,
    int M, int N, int K, int lda, int ldb, int ldc)
{
    constexpr int BM = 128, BN = 128, BK = 16, LDSM = BK + 4; // stride 20 -> conflict-free frags
    __shared__ float As[2][BM][LDSM];
    __shared__ float Bs[2][BN][LDSM];

    const int tid  = threadIdx.x;
    const int bm   = blockIdx.y * BM;
    const int bn   = blockIdx.x * BN;
    const int warp = tid >> 5, lane = tid & 31;
    const int g = lane >> 2, cc = lane & 3;
    const int wm = warp >> 1, wn = warp & 1;  // 4x2 warp grid, warp tile 32x64

    float acc[2][8][4];
#pragma unroll
    for (int mt = 0; mt < 2; mt++)
#pragma unroll
        for (int nt = 0; nt < 8; nt++)
#pragma unroll
            for (int q = 0; q < 4; q++) acc[mt][nt][q] = 0.f;

    const int NT = VEC ? (K / BK) : ((K + BK - 1) / BK);

    auto loadTile = [&](int kt, int buf) {
        const int k0 = kt * BK;
        if (VEC) {
#pragma unroll
            for (int i = 0; i < 2; i++) {
                int idx = tid + i * 256;
                int r = idx >> 2, c4 = (idx & 3) * 4;
                cp16(&As[buf][r][c4], A + (size_t)(bm + r) * lda + k0 + c4, true);
                bool p = (bn + r) < N;
                cp16(&Bs[buf][r][c4], B + (size_t)(bn + r) * ldb + k0 + c4, p);
            }
        } else {
#pragma unroll
            for (int i = 0; i < 8; i++) {
                int idx = tid + i * 256;
                int r = idx >> 4, kk = idx & 15;
                bool pk = (k0 + kk) < K;
                cp4(&As[buf][r][kk], A + (size_t)(bm + r) * lda + k0 + kk, pk);
                bool pb = pk && ((bn + r) < N);
                cp4(&Bs[buf][r][kk], B + (size_t)(bn + r) * ldb + k0 + kk, pb);
            }
        }
    };

    loadTile(0, 0);
    CP_COMMIT;

    for (int kt = 0; kt < NT; kt++) {
        if (kt + 1 < NT) {
            loadTile(kt + 1, (kt + 1) & 1);
            CP_COMMIT;
            CP_WAIT1;
        } else {
            CP_WAIT0;
        }
        __syncthreads();
        const int buf = kt & 1;
#pragma unroll
        for (int ks = 0; ks < BK; ks += 8) {
            unsigned af[2][4], bf[8][2];
#pragma unroll
            for (int mt = 0; mt < 2; mt++) {
                int rb = wm * 32 + mt * 16;
                af[mt][0] = f2tf(As[buf][rb + g][ks + cc]);
                af[mt][1] = f2tf(As[buf][rb + g + 8][ks + cc]);
                af[mt][2] = f2tf(As[buf][rb + g][ks + cc + 4]);
                af[mt][3] = f2tf(As[buf][rb + g + 8][ks + cc + 4]);
            }
#pragma unroll
            for (int nt = 0; nt < 8; nt++) {
                int nb = wn * 64 + nt * 8;
                bf[nt][0] = f2tf(Bs[buf][nb + g][ks + cc]);
                bf[nt][1] = f2tf(Bs[buf][nb + g][ks + cc + 4]);
            }
#pragma unroll
            for (int mt = 0; mt < 2; mt++)
#pragma unroll
                for (int nt = 0; nt < 8; nt++) mma8(acc[mt][nt], af[mt], bf[nt]);
        }
        __syncthreads();
    }

    // epilogue
#pragma unroll
    for (int mt = 0; mt < 2; mt++) {
        int r0 = bm + wm * 32 + mt * 16 + g;
#pragma unroll
        for (int nt = 0; nt < 8; nt++) {
            int c0 = bn + wn * 64 + nt * 8 + cc * 2;
            if (c0 < N) {
                C[(size_t)r0 * ldc + c0]       = acc[mt][nt][0];
                C[(size_t)(r0 + 8) * ldc + c0] = acc[mt][nt][2];
            }
            if (c0 + 1 < N) {
                C[(size_t)r0 * ldc + c0 + 1]       = acc[mt][nt][1];
                C[(size_t)(r0 + 8) * ldc + c0 + 1] = acc[mt][nt][3];
            }
        }
    }
}

// ---------------- depthwise causal conv(4) + silu ----------------
__global__ void conv_silu_k(const float* __restrict__ cw, const float* __restrict__ cb) {
    size_t idx = (size_t)blockIdx.x * 256 + threadIdx.x; // over MTOT*DI
    int dd = (int)(idx & (DI - 1));
    size_t m = idx >> 11;                 // DI = 2^11
    int t = (int)(m & (LSEQ - 1));
    float acc = cb[dd];
#pragma unroll
    for (int k = 0; k < 4; k++) {
        int tt = t - 3 + k;
        if (tt >= 0) acc = fmaf(g_xz[(m - 3 + k) * 4096 + dd], cw[dd * 4 + k], acc);
    }
    g_u[idx] = acc / (1.f + __expf(-acc)); // silu
}

// ---------------- delta = softplus(dt + 2*b_dt)  (in place on g_delta) --------------
__global__ void delta_k(const float* __restrict__ bdt) {
    size_t idx = (size_t)blockIdx.x * 256 + threadIdx.x;
    int dd = (int)(idx & (DI - 1));
    float x = g_delta[idx] + 2.f * bdt[dd];  // reference adds b_dt twice
    g_delta[idx] = fmaxf(x, 0.f) + log1pf(expf(-fabsf(x)));
}

// ---------------- silu(z) into second half of ya ----------------
__global__ void silu_z_k() {
    size_t idx = (size_t)blockIdx.x * 256 + threadIdx.x;
    int dd = (int)(idx & (DI - 1));
    size_t m = idx >> 11;
    float z = g_xz[m * 4096 + DI + dd];
    g_ya[m * 4096 + DI + dd] = z / (1.f + __expf(-z));
}

// ---------------- selective scan ----------------
// 4 threads per (b,d), 4 states each. Block = 256 threads = 64 d's, one b.
// 32-step smem tiles, cp.async double buffered. y reduced with shfl_xor over 4 lanes.
__global__ __launch_bounds__(256) void scan_k(const float* __restrict__ A_log,
                                              const float* __restrict__ Dp) {
    constexpr int T = 32, DBLK = 64, NTIL = LSEQ / T;
    __shared__ float sD[2][T][DBLK];
    __shared__ float sU[2][T][DBLK];
    __shared__ float sBC[2][T][32];

    const int tid = threadIdx.x, lane = tid & 31, warp = tid >> 5;
    const int g = lane >> 2, sub = lane & 3;
    const int pair = warp * 8 + g;            // 0..63
    const int b = blockIdx.y;
    const int d0 = blockIdx.x * DBLK;
    const int d = d0 + pair;

    float a[4], h[4];
#pragma unroll
    for (int j = 0; j < 4; j++) {
        a[j] = -expf(A_log[d * DSTATE + sub * 4 + j]);
        h[j] = 0.f;
    }
    const float Dd = Dp[d];
    const size_t mbase = (size_t)b * LSEQ;

    auto loadTile = [&](int nt, int buf) {
        const int t0 = nt * T;
#pragma unroll
        for (int i = 0; i < 2; i++) {
            int idx = tid + i * 256;
            int r = idx >> 4, c4 = (idx & 15) * 4;
            size_t m = mbase + t0 + r;
            cp16(&sD[buf][r][c4], g_delta + m * DI + d0 + c4, true);
            cp16(&sU[buf][r][c4], g_u + m * DI + d0 + c4, true);
        }
#pragma unroll
        for (int i = 0; i < 4; i++) {
            int idx = tid + i * 256;
            int r = idx >> 5, c = idx & 31;
            size_t m = mbase + t0 + r;
            cp4(&sBC[buf][r][c], g_params + m * NPAR + DTR + c, true);
        }
    };

    loadTile(0, 0);
    CP_COMMIT;

    for (int nt = 0; nt < NTIL; nt++) {
        if (nt + 1 < NTIL) {
            loadTile(nt + 1, (nt + 1) & 1);
            CP_COMMIT;
            CP_WAIT1;
        } else {
            CP_WAIT0;
        }
        __syncthreads();
        const int buf = nt & 1;
        const int t0 = nt * T;
#pragma unroll 8
        for (int t = 0; t < T; t++) {
            float dl = sD[buf][t][pair];
            float uu = sU[buf][t][pair];
            float4 Bv = *(const float4*)&sBC[buf][t][sub * 4];
            float4 Cv = *(const float4*)&sBC[buf][t][16 + sub * 4];
            float w = dl * uu;
            float y;
            h[0] = fmaf(__expf(dl * a[0]), h[0], w * Bv.x); y  = h[0] * Cv.x;
            h[1] = fmaf(__expf(dl * a[1]), h[1], w * Bv.y); y += h[1] * Cv.y;
            h[2] = fmaf(__expf(dl * a[2]), h[2], w * Bv.z); y += h[2] * Cv.z;
            h[3] = fmaf(__expf(dl * a[3]), h[3], w * Bv.w); y += h[3] * Cv.w;
            y += __shfl_xor_sync(0xffffffffu, y, 1);
            y += __shfl_xor_sync(0xffffffffu, y, 2);
            if (sub == 0)
                g_ya[(mbase + t0 + t) * 4096 + d] = fmaf(Dd, uu, y);
        }
        __syncthreads();
    }
}

// ---------------- launch ----------------
extern "C" void kernel_launch(void* const* d_in, const int* in_sizes, int n_in,
                              void* d_out, int out_size) {
    const float* x      = (const float*)d_in[0];
    const float* W_in   = (const float*)d_in[1];
    const float* W_out  = (const float*)d_in[2];
    const float* conv_w = (const float*)d_in[3];
    const float* conv_b = (const float*)d_in[4];
    const float* W_x    = (const float*)d_in[5];
    const float* W_dt   = (const float*)d_in[6];
    const float* b_dt   = (const float*)d_in[7];
    const float* A_log  = (const float*)d_in[8];
    const float* D_par  = (const float*)d_in[9];
    float* out = (float*)d_out;

    float *xz, *u, *delta, *params, *ya;
    cudaGetSymbolAddress((void**)&xz, g_xz);
    cudaGetSymbolAddress((void**)&u, g_u);
    cudaGetSymbolAddress((void**)&delta, g_delta);
    cudaGetSymbolAddress((void**)&params, g_params);
    cudaGetSymbolAddress((void**)&ya, g_ya);

    const int EW_BLOCKS = (int)(((size_t)MTOT * DI) / 256); // 131072

    // 1) xz = x @ W_in^T   (16384 x 4096, K=1024)
    gemm_tn<true><<<dim3(4096 / 128, MTOT / 128), 256>>>(x, W_in, xz,
                                                         MTOT, 4096, 1024, 1024, 1024, 4096);
    // 2) u = silu(conv(x_in))
    conv_silu_k<<<EW_BLOCKS, 256>>>(conv_w, conv_b);
    // 3) params = u @ W_x^T  (N=97, K=2048)
    gemm_tn<true><<<dim3(1, MTOT / 128), 256>>>(u, W_x, params,
                                                MTOT, NPAR, DI, DI, DI, NPAR);
    // 4) dt2 = params[:, :65] @ W_dt^T  (N=2048, K=65; scalar path: lda=97, ragged K)
    gemm_tn<false><<<dim3(DI / 128, MTOT / 128), 256>>>(params, W_dt, delta,
                                                        MTOT, DI, DTR, NPAR, DTR, DI);
    // 5) delta = softplus(dt2 + 2*b_dt) (in place)
    delta_k<<<EW_BLOCKS, 256>>>(b_dt);
    // 6) ya[:, 2048:] = silu(z)
    silu_z_k<<<EW_BLOCKS, 256>>>();
    // 7) ya[:, :2048] = selective scan + D*u
    scan_k<<<dim3(DI / 64, BQ), 256>>>(A_log, D_par);
    // 8) out = ya @ W_out^T  (N=1024, K=4096)
    gemm_tn<true><<<dim3(1024 / 128, MTOT / 128), 256>>>(ya, W_out, out,
                                                         MTOT, DM, 4096, 4096, 4096, DM);
}

// round 11
// speedup vs baseline: 1.2383x; 1.2383x over previous
#include <cuda_runtime.h>
#include <cstdint>

// ---------------- problem constants ----------------
#define DI     2048
#define DM     1024
#define LSEQ   4096
#define BQ     4
#define MTOT   (BQ*LSEQ)       // 16384
#define DSTATE 16
#define DTR    65
#define KPAD   80              // dt_rank padded to BK multiple
#define LDP    128             // params leading dim (padded)

// ---------------- scratch ----------------
__device__ float g_xz[(size_t)MTOT * DI];     // x_in (raw fp32 for conv)
__device__ float g_u[(size_t)MTOT * DI];      // silu(conv(x_in)), fp32
__device__ float g_delta[(size_t)MTOT * DI];  // softplus(dt + 2 b_dt), fp32
__device__ float g_params[(size_t)MTOT * LDP];
__device__ float g_ya[(size_t)MTOT * 4096];   // [y_ssm | silu(z)] tf32-rounded
__device__ float g_xr[(size_t)MTOT * DM];     // x tf32-rounded
__device__ float g_wi[4096 * 1024];           // W_in tf32-rounded
__device__ float g_wo[1024 * 4096];           // W_out tf32-rounded
__device__ float g_wdtp[DI * KPAD];           // W_dt zero-padded (raw)

// ---------------- PTX helpers ----------------
__device__ __forceinline__ void cp16(void* sm, const void* gm, bool p) {
    unsigned s = (unsigned)__cvta_generic_to_shared(sm);
    int n = p ? 16 : 0;
    asm volatile("cp.async.ca.shared.global [%0], [%1], 16, %2;\n" ::"r"(s), "l"(gm), "r"(n));
}
__device__ __forceinline__ void cp16g(void* sm, const void* gm) {
    unsigned s = (unsigned)__cvta_generic_to_shared(sm);
    asm volatile("cp.async.cg.shared.global [%0], [%1], 16;\n" ::"r"(s), "l"(gm));
}
__device__ __forceinline__ void cp4(void* sm, const void* gm, bool p) {
    unsigned s = (unsigned)__cvta_generic_to_shared(sm);
    int n = p ? 4 : 0;
    asm volatile("cp.async.ca.shared.global [%0], [%1], 4, %2;\n" ::"r"(s), "l"(gm), "r"(n));
}
#define CP_COMMIT asm volatile("cp.async.commit_group;\n" ::: "memory")
#define CP_WAIT1  asm volatile("cp.async.wait_group 1;\n" ::: "memory")
#define CP_WAIT0  asm volatile("cp.async.wait_group 0;\n" ::: "memory")

__device__ __forceinline__ unsigned f2tf(float x) {
    unsigned r;
    asm("cvt.rna.tf32.f32 %0, %1;" : "=r"(r) : "f"(x));
    return r;
}
__device__ __forceinline__ float siluf(float v) { return v / (1.f + __expf(-v)); }
__device__ __forceinline__ float softplus2(float v, float b) {
    float x = v + 2.f * b;   // reference adds b_dt twice
    return fmaxf(x, 0.f) + log1pf(expf(-fabsf(x)));
}
__device__ __forceinline__ void mma8(float c[4], const unsigned a[4], const unsigned b[2]) {
    asm volatile(
        "mma.sync.aligned.m16n8k8.row.col.f32.tf32.tf32.f32 "
        "{%0,%1,%2,%3}, {%4,%5,%6,%7}, {%8,%9}, {%0,%1,%2,%3};\n"
        : "+f"(c[0]), "+f"(c[1]), "+f"(c[2]), "+f"(c[3])
        : "r"(a[0]), "r"(a[1]), "r"(a[2]), "r"(a[3]), "r"(b[0]), "r"(b[1]));
}

// ============ FAST tf32 GEMM (inputs PRE-ROUNDED to tf32; no in-loop CVT) =========
// C[m,n] = sum_k A[m,k]*B[n,k].  BM=BN=128, BK=32, 256 thr, 2-stage cp.async.
// EPI=0: plain fp32 store to C0/ldc.
// EPI=1: (GEMM1) n<DI -> raw x_in to g_xz ; n>=DI -> f2tf(silu) to g_ya.
#define BKF   32
#define LDSF  36
#define SMEM_F (2 * 2 * 128 * LDSF * 4)   // 73728 B
template <int EPI>
__global__ __launch_bounds__(256, 2) void gemm_fast(
    const float* __restrict__ A, const float* __restrict__ B,
    float* __restrict__ C0, int K, int lda, int ldb, int ldc)
{
    constexpr int BM = 128, BN = 128, BK = BKF, LDSM = LDSF;
    extern __shared__ float smf[];
    float (*As)[BM][LDSM] = (float(*)[BM][LDSM])smf;
    float (*Bs)[BM][LDSM] = (float(*)[BM][LDSM])(smf + 2 * BM * LDSM);

    const int tid = threadIdx.x;
    const int bm = blockIdx.y * BM, bn = blockIdx.x * BN;
    const int warp = tid >> 5, lane = tid & 31;
    const int g = lane >> 2, cc = lane & 3;
    const int wm = warp >> 1, wn = warp & 1;   // 4x2 warps, warp tile 32x64

    float acc[2][8][4];
#pragma unroll
    for (int mt = 0; mt < 2; mt++)
#pragma unroll
        for (int nt = 0; nt < 8; nt++)
#pragma unroll
            for (int q = 0; q < 4; q++) acc[mt][nt][q] = 0.f;

    const int NT = K / BK;
    auto loadTile = [&](int kt, int buf) {
        const int k0 = kt * BK;
#pragma unroll
        for (int i = 0; i < 4; i++) {          // 128 rows x 8 float4 per matrix
            int idx = tid + i * 256;
            int r = idx >> 3, c4 = (idx & 7) * 4;
            cp16g(&As[buf][r][c4], A + (size_t)(bm + r) * lda + k0 + c4);
            cp16g(&Bs[buf][r][c4], B + (size_t)(bn + r) * ldb + k0 + c4);
        }
    };

    loadTile(0, 0);
    CP_COMMIT;
    for (int kt = 0; kt < NT; kt++) {
        if (kt + 1 < NT) { loadTile(kt + 1, (kt + 1) & 1); CP_COMMIT; CP_WAIT1; }
        else             { CP_WAIT0; }
        __syncthreads();
        const int buf = kt & 1;
#pragma unroll
        for (int ks = 0; ks < BK; ks += 8) {
            unsigned af[2][4], bf[8][2];
#pragma unroll
            for (int mt = 0; mt < 2; mt++) {
                int rb = wm * 32 + mt * 16;
                af[mt][0] = __float_as_uint(As[buf][rb + g][ks + cc]);
                af[mt][1] = __float_as_uint(As[buf][rb + g + 8][ks + cc]);
                af[mt][2] = __float_as_uint(As[buf][rb + g][ks + cc + 4]);
                af[mt][3] = __float_as_uint(As[buf][rb + g + 8][ks + cc + 4]);
            }
#pragma unroll
            for (int nt = 0; nt < 8; nt++) {
                int nb = wn * 64 + nt * 8;
                bf[nt][0] = __float_as_uint(Bs[buf][nb + g][ks + cc]);
                bf[nt][1] = __float_as_uint(Bs[buf][nb + g][ks + cc + 4]);
            }
#pragma unroll
            for (int mt = 0; mt < 2; mt++)
#pragma unroll
                for (int nt = 0; nt < 8; nt++) mma8(acc[mt][nt], af[mt], bf[nt]);
        }
        __syncthreads();
    }

    // epilogue
#pragma unroll
    for (int mt = 0; mt < 2; mt++) {
        int r0 = bm + wm * 32 + mt * 16 + g;
#pragma unroll
        for (int nt = 0; nt < 8; nt++) {
            int c0 = bn + wn * 64 + nt * 8 + cc * 2;
#pragma unroll
            for (int e = 0; e < 2; e++) {
                int c = c0 + e;
                float v0 = acc[mt][nt][e], v1 = acc[mt][nt][e + 2];
                if constexpr (EPI == 0) {
                    C0[(size_t)r0 * ldc + c] = v0;
                    C0[(size_t)(r0 + 8) * ldc + c] = v1;
                } else {
                    if (c < DI) {   // x_in half: raw fp32 for conv
                        g_xz[(size_t)r0 * DI + c] = v0;
                        g_xz[(size_t)(r0 + 8) * DI + c] = v1;
                    } else {        // z half: tf32(silu(z)) into ya
                        g_ya[(size_t)r0 * 4096 + c] = __uint_as_float(f2tf(siluf(v0)));
                        g_ya[(size_t)(r0 + 8) * 4096 + c] = __uint_as_float(f2tf(siluf(v1)));
                    }
                }
            }
        }
    }
}

// ============ tf32 GEMM with in-loop CVT (raw fp32 inputs; small shapes) ==========
template <int EPI>   // 0: plain store; 1: softplus(v + 2*bias[n])
__global__ __launch_bounds__(256) void gemm_tn(
    const float* __restrict__ A, const float* __restrict__ B, float* __restrict__ C,
    const float* __restrict__ bias, int M, int N, int K, int lda, int ldb, int ldc)
{
    constexpr int BM = 128, BN = 128, BK = 16, LDSM = BK + 4;
    __shared__ float As[2][BM][LDSM];
    __shared__ float Bs[2][BN][LDSM];

    const int tid = threadIdx.x;
    const int bm = blockIdx.y * BM, bn = blockIdx.x * BN;
    const int warp = tid >> 5, lane = tid & 31;
    const int g = lane >> 2, cc = lane & 3;
    const int wm = warp >> 1, wn = warp & 1;

    float acc[2][8][4];
#pragma unroll
    for (int mt = 0; mt < 2; mt++)
#pragma unroll
        for (int nt = 0; nt < 8; nt++)
#pragma unroll
            for (int q = 0; q < 4; q++) acc[mt][nt][q] = 0.f;

    const int NT = K / BK;
    auto loadTile = [&](int kt, int buf) {
        const int k0 = kt * BK;
#pragma unroll
        for (int i = 0; i < 2; i++) {
            int idx = tid + i * 256;
            int r = idx >> 2, c4 = (idx & 3) * 4;
            cp16(&As[buf][r][c4], A + (size_t)(bm + r) * lda + k0 + c4, true);
            bool p = (bn + r) < N;
            cp16(&Bs[buf][r][c4], B + (size_t)(bn + r) * ldb + k0 + c4, p);
        }
    };

    loadTile(0, 0);
    CP_COMMIT;
    for (int kt = 0; kt < NT; kt++) {
        if (kt + 1 < NT) { loadTile(kt + 1, (kt + 1) & 1); CP_COMMIT; CP_WAIT1; }
        else             { CP_WAIT0; }
        __syncthreads();
        const int buf = kt & 1;
#pragma unroll
        for (int ks = 0; ks < BK; ks += 8) {
            unsigned af[2][4], bf[8][2];
#pragma unroll
            for (int mt = 0; mt < 2; mt++) {
                int rb = wm * 32 + mt * 16;
                af[mt][0] = f2tf(As[buf][rb + g][ks + cc]);
                af[mt][1] = f2tf(As[buf][rb + g + 8][ks + cc]);
                af[mt][2] = f2tf(As[buf][rb + g][ks + cc + 4]);
                af[mt][3] = f2tf(As[buf][rb + g + 8][ks + cc + 4]);
            }
#pragma unroll
            for (int nt = 0; nt < 8; nt++) {
                int nb = wn * 64 + nt * 8;
                bf[nt][0] = f2tf(Bs[buf][nb + g][ks + cc]);
                bf[nt][1] = f2tf(Bs[buf][nb + g][ks + cc + 4]);
            }
#pragma unroll
            for (int mt = 0; mt < 2; mt++)
#pragma unroll
                for (int nt = 0; nt < 8; nt++) mma8(acc[mt][nt], af[mt], bf[nt]);
        }
        __syncthreads();
    }

#pragma unroll
    for (int mt = 0; mt < 2; mt++) {
        int r0 = bm + wm * 32 + mt * 16 + g;
#pragma unroll
        for (int nt = 0; nt < 8; nt++) {
            int c0 = bn + wn * 64 + nt * 8 + cc * 2;
#pragma unroll
            for (int e = 0; e < 2; e++) {
                int c = c0 + e;
                if (c < N) {
                    float v0 = acc[mt][nt][e], v1 = acc[mt][nt][e + 2];
                    if constexpr (EPI == 1) {
                        float b = bias[c];
                        v0 = softplus2(v0, b);
                        v1 = softplus2(v1, b);
                    }
                    C[(size_t)r0 * ldc + c] = v0;
                    C[(size_t)(r0 + 8) * ldc + c] = v1;
                }
            }
        }
    }
}

// ---------------- elementwise kernels ----------------
__global__ void round4_k(const float* __restrict__ s, float* __restrict__ d) {
    size_t i = (size_t)blockIdx.x * 256 + threadIdx.x;
    float4 v = ((const float4*)s)[i];
    v.x = __uint_as_float(f2tf(v.x)); v.y = __uint_as_float(f2tf(v.y));
    v.z = __uint_as_float(f2tf(v.z)); v.w = __uint_as_float(f2tf(v.w));
    ((float4*)d)[i] = v;
}
__global__ void wdtpad_k(const float* __restrict__ w) {
    int i = blockIdx.x * 256 + threadIdx.x;   // DI*KPAD
    int r = i / KPAD, c = i - r * KPAD;
    g_wdtp[i] = (c < DTR) ? w[r * DTR + c] : 0.f;
}
__global__ void conv_silu_k(const float* __restrict__ cw, const float* __restrict__ cb) {
    size_t idx = (size_t)blockIdx.x * 256 + threadIdx.x;   // MTOT*DI
    int dd = (int)(idx & (DI - 1));
    size_t m = idx >> 11;
    int t = (int)(m & (LSEQ - 1));
    float acc = cb[dd];
#pragma unroll
    for (int k = 0; k < 4; k++) {
        int tt = t - 3 + k;
        if (tt >= 0) acc = fmaf(g_xz[(m - 3 + k) * DI + dd], cw[dd * 4 + k], acc);
    }
    g_u[idx] = siluf(acc);
}

// ---------------- selective scan ----------------
__global__ __launch_bounds__(256) void scan_k(const float* __restrict__ A_log,
                                              const float* __restrict__ Dp) {
    constexpr int T = 32, DBLK = 64, NTIL = LSEQ / T;
    __shared__ float sD[2][T][DBLK];
    __shared__ float sU[2][T][DBLK];
    __shared__ float sBC[2][T][32];

    const int tid = threadIdx.x, lane = tid & 31, warp = tid >> 5;
    const int g = lane >> 2, sub = lane & 3;
    const int pair = warp * 8 + g;
    const int b = blockIdx.y;
    const int d0 = blockIdx.x * DBLK;
    const int d = d0 + pair;

    float a[4], h[4];
#pragma unroll
    for (int j = 0; j < 4; j++) {
        a[j] = -expf(A_log[d * DSTATE + sub * 4 + j]);
        h[j] = 0.f;
    }
    const float Dd = Dp[d];
    const size_t mbase = (size_t)b * LSEQ;

    auto loadTile = [&](int nt, int buf) {
        const int t0 = nt * T;
#pragma unroll
        for (int i = 0; i < 2; i++) {
            int idx = tid + i * 256;
            int r = idx >> 4, c4 = (idx & 15) * 4;
            size_t m = mbase + t0 + r;
            cp16(&sD[buf][r][c4], g_delta + m * DI + d0 + c4, true);
            cp16(&sU[buf][r][c4], g_u + m * DI + d0 + c4, true);
        }
#pragma unroll
        for (int i = 0; i < 4; i++) {
            int idx = tid + i * 256;
            int r = idx >> 5, c = idx & 31;
            size_t m = mbase + t0 + r;
            cp4(&sBC[buf][r][c], g_params + m * LDP + DTR + c, true);
        }
    };

    loadTile(0, 0);
    CP_COMMIT;

    for (int nt = 0; nt < NTIL; nt++) {
        if (nt + 1 < NTIL) { loadTile(nt + 1, (nt + 1) & 1); CP_COMMIT; CP_WAIT1; }
        else               { CP_WAIT0; }
        __syncthreads();
        const int buf = nt & 1;
        const int t0 = nt * T;
#pragma unroll 8
        for (int t = 0; t < T; t++) {
            float dl = sD[buf][t][pair];
            float uu = sU[buf][t][pair];
            float4 Bv = *(const float4*)&sBC[buf][t][sub * 4];
            float4 Cv = *(const float4*)&sBC[buf][t][16 + sub * 4];
            float w = dl * uu;
            float y;
            h[0] = fmaf(__expf(dl * a[0]), h[0], w * Bv.x); y  = h[0] * Cv.x;
            h[1] = fmaf(__expf(dl * a[1]), h[1], w * Bv.y); y += h[1] * Cv.y;
            h[2] = fmaf(__expf(dl * a[2]), h[2], w * Bv.z); y += h[2] * Cv.z;
            h[3] = fmaf(__expf(dl * a[3]), h[3], w * Bv.w); y += h[3] * Cv.w;
            y += __shfl_xor_sync(0xffffffffu, y, 1);
            y += __shfl_xor_sync(0xffffffffu, y, 2);
            if (sub == 0)
                g_ya[(mbase + t0 + t) * 4096 + d] =
                    __uint_as_float(f2tf(fmaf(Dd, uu, y)));
        }
        __syncthreads();
    }
}

// ---------------- launch ----------------
extern "C" void kernel_launch(void* const* d_in, const int* in_sizes, int n_in,
                              void* d_out, int out_size) {
    const float* x      = (const float*)d_in[0];
    const float* W_in   = (const float*)d_in[1];
    const float* W_out  = (const float*)d_in[2];
    const float* conv_w = (const float*)d_in[3];
    const float* conv_b = (const float*)d_in[4];
    const float* W_x    = (const float*)d_in[5];
    const float* W_dt   = (const float*)d_in[6];
    const float* b_dt   = (const float*)d_in[7];
    const float* A_log  = (const float*)d_in[8];
    const float* D_par  = (const float*)d_in[9];
    float* out = (float*)d_out;

    float *u, *delta, *params, *ya, *xr, *wi, *wo, *wdtp;
    cudaGetSymbolAddress((void**)&u, g_u);
    cudaGetSymbolAddress((void**)&delta, g_delta);
    cudaGetSymbolAddress((void**)&params, g_params);
    cudaGetSymbolAddress((void**)&ya, g_ya);
    cudaGetSymbolAddress((void**)&xr, g_xr);
    cudaGetSymbolAddress((void**)&wi, g_wi);
    cudaGetSymbolAddress((void**)&wo, g_wo);
    cudaGetSymbolAddress((void**)&wdtp, g_wdtp);

    cudaFuncSetAttribute(gemm_fast<0>, cudaFuncAttributeMaxDynamicSharedMemorySize, SMEM_F);
    cudaFuncSetAttribute(gemm_fast<1>, cudaFuncAttributeMaxDynamicSharedMemorySize, SMEM_F);

    // pre-round tensor-core inputs to tf32 (exactness: HMMA truncation is identity)
    round4_k<<<MTOT * DM / 4 / 256, 256>>>(x, xr);
    round4_k<<<4096 * 1024 / 4 / 256, 256>>>(W_in, wi);
    round4_k<<<1024 * 4096 / 4 / 256, 256>>>(W_out, wo);
    wdtpad_k<<<DI * KPAD / 256, 256>>>(W_dt);

    // 1) xz = x @ W_in^T  (no-CVT fast GEMM); epilogue splits x_in / tf32(silu(z))
    gemm_fast<1><<<dim3(4096 / 128, MTOT / 128), 256, SMEM_F>>>(
        xr, wi, nullptr, 1024, 1024, 1024, 0);
    // 2) u = silu(conv(x_in))  (fp32)
    conv_silu_k<<<(int)((size_t)MTOT * DI / 256), 256>>>(conv_w, conv_b);
    // 3) params = u @ W_x^T  (raw inputs -> CVT path; ldc padded to 128)
    gemm_tn<0><<<dim3(1, MTOT / 128), 256>>>(u, W_x, params, nullptr,
                                             MTOT, 97, DI, DI, DI, LDP);
    // 4) delta = softplus(params[:, :65] @ W_dt^T + 2*b_dt)  (K padded to 80, fused)
    gemm_tn<1><<<dim3(DI / 128, MTOT / 128), 256>>>(params, wdtp, delta, b_dt,
                                                    MTOT, DI, KPAD, LDP, KPAD, DI);
    // 5) ya[:, :2048] = selective scan + D*u  (tf32-rounded stores)
    scan_k<<<dim3(DI / 64, BQ), 256>>>(A_log, D_par);
    // 6) out = ya @ W_out^T  (no-CVT fast GEMM)
    gemm_fast<0><<<dim3(1024 / 128, MTOT / 128), 256, SMEM_F>>>(
        ya, wo, out, 4096, 4096, 4096, DM);
}